// round 1
// baseline (speedup 1.0000x reference)
#include <cuda_runtime.h>

#define FDIM 128

// Scratch for per-node precomputed A = x@W1[0:128], B = x@W1[128:256]
__device__ float g_A[50000 * FDIM];
__device__ float g_B[50000 * FDIM];

// ---------------------------------------------------------------------------
// Kernel 1: A[n] = x[n] @ W1a, B[n] = x[n] @ W1b   (per-node precompute)
// 256 threads, 128-row tile, 8x8 register micro-tile per thread.
// ---------------------------------------------------------------------------
extern "C" __global__ void __launch_bounds__(256, 1)
k_precompute(const float* __restrict__ x, const float* __restrict__ W1, int n_nodes)
{
    extern __shared__ float smem[];
    float* xs = smem;            // [128][128] x tile TRANSPOSED: xs[k*128 + row]
    float* ws = smem + 16384;    // [128][128] W block: ws[k*128 + f]

    const int tid  = threadIdx.x;
    const int ty   = tid >> 4;
    const int tx   = tid & 15;
    const int row0 = blockIdx.x * 128;

    // load x tile transposed
    #pragma unroll
    for (int it = 0; it < 16; ++it) {
        int idx = it * 256 + tid;
        int r   = idx >> 5;
        int c4  = idx & 31;
        int grow = row0 + r;
        float4 v = make_float4(0.f, 0.f, 0.f, 0.f);
        if (grow < n_nodes) v = reinterpret_cast<const float4*>(x)[grow * 32 + c4];
        xs[(c4 * 4 + 0) * 128 + r] = v.x;
        xs[(c4 * 4 + 1) * 128 + r] = v.y;
        xs[(c4 * 4 + 2) * 128 + r] = v.z;
        xs[(c4 * 4 + 3) * 128 + r] = v.w;
    }

    for (int part = 0; part < 2; ++part) {
        __syncthreads();
        const float* Wblk = W1 + part * 128 * FDIM;
        #pragma unroll
        for (int it = 0; it < 16; ++it) {
            int idx = it * 256 + tid;
            reinterpret_cast<float4*>(ws)[idx] =
                reinterpret_cast<const float4*>(Wblk)[idx];
        }
        __syncthreads();

        float c[8][8];
        #pragma unroll
        for (int i = 0; i < 8; ++i)
            #pragma unroll
            for (int j = 0; j < 8; ++j) c[i][j] = 0.f;

        #pragma unroll 8
        for (int k = 0; k < 128; ++k) {
            float a[8], b[8];
            *(float4*)&a[0] = *(const float4*)&xs[k * 128 + ty * 8];
            *(float4*)&a[4] = *(const float4*)&xs[k * 128 + ty * 8 + 4];
            *(float4*)&b[0] = *(const float4*)&ws[k * 128 + tx * 8];
            *(float4*)&b[4] = *(const float4*)&ws[k * 128 + tx * 8 + 4];
            #pragma unroll
            for (int i = 0; i < 8; ++i)
                #pragma unroll
                for (int j = 0; j < 8; ++j)
                    c[i][j] = fmaf(a[i], b[j], c[i][j]);
        }

        float* dst = (part == 0) ? g_A : g_B;
        #pragma unroll
        for (int i = 0; i < 8; ++i) {
            int grow = row0 + ty * 8 + i;
            if (grow < n_nodes) {
                float4* o = reinterpret_cast<float4*>(dst + grow * FDIM + tx * 8);
                o[0] = make_float4(c[i][0], c[i][1], c[i][2], c[i][3]);
                o[1] = make_float4(c[i][4], c[i][5], c[i][6], c[i][7]);
            }
        }
    }
}

// ---------------------------------------------------------------------------
// Kernel 2: per pair p:
//   pre = w_ij[p] @ W1c + A[idx_i[p]] + B[idx_j[p]] + b1
//   out[p] = silu(pre) . W2 + b2
// 128 pairs per block, 256 threads, 8x8 micro-tile GEMM + fused epilogue.
// ---------------------------------------------------------------------------
extern "C" __global__ void __launch_bounds__(256, 1)
k_pairs(const float* __restrict__ w_ij,
        const float* __restrict__ W1,
        const float* __restrict__ b1,
        const float* __restrict__ W2,
        const float* __restrict__ b2,
        const int* __restrict__ idx_i,
        const int* __restrict__ idx_j,
        float* __restrict__ out,
        int n_pairs)
{
    extern __shared__ float smem[];
    float* ws  = smem;             // W1c [k][f]
    float* sA  = smem + 16384;     // w tile transposed [k][p]; later addend [p][f]
    float* red = smem + 32768;     // [128][17] row partial sums
    int*   ii  = (int*)(smem + 32768 + 2176);
    int*   jj  = ii + 128;

    const int tid = threadIdx.x;
    const int ty  = tid >> 4;
    const int tx  = tid & 15;
    const int p0  = blockIdx.x * 128;

    // load W1c (rows 256..383 of W1)
    const float* W1c = W1 + 256 * FDIM;
    #pragma unroll
    for (int it = 0; it < 16; ++it) {
        int idx = it * 256 + tid;
        reinterpret_cast<float4*>(ws)[idx] =
            reinterpret_cast<const float4*>(W1c)[idx];
    }
    // load w_ij tile transposed
    #pragma unroll
    for (int it = 0; it < 16; ++it) {
        int idx = it * 256 + tid;
        int r   = idx >> 5;
        int c4  = idx & 31;
        int gp  = p0 + r;
        float4 v = make_float4(0.f, 0.f, 0.f, 0.f);
        if (gp < n_pairs) v = reinterpret_cast<const float4*>(w_ij)[gp * 32 + c4];
        sA[(c4 * 4 + 0) * 128 + r] = v.x;
        sA[(c4 * 4 + 1) * 128 + r] = v.y;
        sA[(c4 * 4 + 2) * 128 + r] = v.z;
        sA[(c4 * 4 + 3) * 128 + r] = v.w;
    }
    // load pair indices
    if (tid < 128) {
        int gp = p0 + tid;
        ii[tid] = (gp < n_pairs) ? idx_i[gp] : 0;
    } else {
        int gp = p0 + (tid - 128);
        jj[tid - 128] = (gp < n_pairs) ? idx_j[gp] : 0;
    }
    // per-thread b1 / W2 fragments (cols tx*8 .. tx*8+7)
    float b1r[8], w2r[8];
    #pragma unroll
    for (int j = 0; j < 8; ++j) {
        b1r[j] = b1[tx * 8 + j];
        w2r[j] = W2[tx * 8 + j];
    }
    __syncthreads();

    // GEMM: pre(128x128) = w_tile(128x128) @ W1c(128x128)
    float c[8][8];
    #pragma unroll
    for (int i = 0; i < 8; ++i)
        #pragma unroll
        for (int j = 0; j < 8; ++j) c[i][j] = 0.f;

    #pragma unroll 8
    for (int k = 0; k < 128; ++k) {
        float a[8], b[8];
        *(float4*)&a[0] = *(const float4*)&sA[k * 128 + ty * 8];
        *(float4*)&a[4] = *(const float4*)&sA[k * 128 + ty * 8 + 4];
        *(float4*)&b[0] = *(const float4*)&ws[k * 128 + tx * 8];
        *(float4*)&b[4] = *(const float4*)&ws[k * 128 + tx * 8 + 4];
        #pragma unroll
        for (int i = 0; i < 8; ++i)
            #pragma unroll
            for (int j = 0; j < 8; ++j)
                c[i][j] = fmaf(a[i], b[j], c[i][j]);
    }
    __syncthreads();   // all reads of sA done

    // build addend tile in sA (row-major): sA[r][f] = A[ii[r]][f] + B[jj[r]][f]
    #pragma unroll
    for (int it = 0; it < 16; ++it) {
        int idx = it * 256 + tid;
        int r   = idx >> 5;
        int c4  = idx & 31;
        float4 va = reinterpret_cast<const float4*>(g_A)[ii[r] * 32 + c4];
        float4 vb = reinterpret_cast<const float4*>(g_B)[jj[r] * 32 + c4];
        reinterpret_cast<float4*>(sA)[idx] =
            make_float4(va.x + vb.x, va.y + vb.y, va.z + vb.z, va.w + vb.w);
    }
    __syncthreads();

    // fused epilogue: add, silu, dot with W2 (partial per 8-col slab)
    #pragma unroll
    for (int i = 0; i < 8; ++i) {
        int r = ty * 8 + i;
        float ad[8];
        *(float4*)&ad[0] = *(const float4*)&sA[r * 128 + tx * 8];
        *(float4*)&ad[4] = *(const float4*)&sA[r * 128 + tx * 8 + 4];
        float part = 0.f;
        #pragma unroll
        for (int j = 0; j < 8; ++j) {
            float v = c[i][j] + ad[j] + b1r[j];
            float h = __fdividef(v, 1.0f + __expf(-v));   // silu
            part = fmaf(h, w2r[j], part);
        }
        red[r * 17 + tx] = part;
    }
    __syncthreads();

    // reduce 16 partials per row, add b2, write out
    if (tid < 128) {
        float s = 0.f;
        #pragma unroll
        for (int t = 0; t < 16; ++t) s += red[tid * 17 + t];
        int gp = p0 + tid;
        if (gp < n_pairs) out[gp] = s + b2[0];
    }
}

// ---------------------------------------------------------------------------
extern "C" void kernel_launch(void* const* d_in, const int* in_sizes, int n_in,
                              void* d_out, int out_size)
{
    const float* x     = (const float*)d_in[0];
    const float* w_ij  = (const float*)d_in[1];
    const float* W1    = (const float*)d_in[2];
    const float* b1    = (const float*)d_in[3];
    const float* W2    = (const float*)d_in[4];
    const float* b2    = (const float*)d_in[5];
    const int*   idx_i = (const int*)d_in[6];
    const int*   idx_j = (const int*)d_in[7];
    float* out = (float*)d_out;

    const int n_nodes = in_sizes[0] / FDIM;
    const int n_pairs = out_size;

    const int SMEM1 = 2 * 16384 * sizeof(float);                        // 128 KB
    const int SMEM2 = (16384 + 16384 + 128 * 17) * sizeof(float) + 256 * sizeof(int);

    cudaFuncSetAttribute(k_precompute, cudaFuncAttributeMaxDynamicSharedMemorySize, SMEM1);
    cudaFuncSetAttribute(k_pairs,      cudaFuncAttributeMaxDynamicSharedMemorySize, SMEM2);

    int g1 = (n_nodes + 127) / 128;
    int g2 = (n_pairs + 127) / 128;

    k_precompute<<<g1, 256, SMEM1>>>(x, W1, n_nodes);
    k_pairs<<<g2, 256, SMEM2>>>(w_ij, W1, b1, W2, b2, idx_i, idx_j, out, n_pairs);
}

// round 3
// speedup vs baseline: 2.4552x; 2.4552x over previous
#include <cuda_runtime.h>
#include <cuda_bf16.h>
#include <cstdint>

#define FDIM 128

// per-node precomputed A = x@W1a (gather by idx_i), B = x@W1b (gather by idx_j)
__device__ float g_A[50000 * FDIM];
__device__ float g_B[50000 * FDIM];
// bf16 hi/lo swizzled images of W1a^T, W1b^T, W1c^T : [part][hi/lo][32KB]
__device__ __align__(16) unsigned g_img[3][2][8192];
// silu quadratic table: 256 bins over [-8,8], (c0,c1,c2,0)
__device__ float4 g_tab[256];

// ---------------------------------------------------------------------------
// helpers
// ---------------------------------------------------------------------------
__device__ __forceinline__ uint32_t smem_u32(const void* p) {
    uint32_t a;
    asm("{ .reg .u64 t; cvta.to.shared.u64 t, %1; cvt.u32.u64 %0, t; }"
        : "=r"(a) : "l"(p));
    return a;
}
__device__ __forceinline__ void ldsm_x4(uint32_t& a0, uint32_t& a1,
                                        uint32_t& a2, uint32_t& a3, uint32_t addr) {
    asm volatile("ldmatrix.sync.aligned.m8n8.x4.shared.b16 {%0,%1,%2,%3}, [%4];"
                 : "=r"(a0), "=r"(a1), "=r"(a2), "=r"(a3) : "r"(addr));
}
__device__ __forceinline__ void ldsm_x2(uint32_t& b0, uint32_t& b1, uint32_t addr) {
    asm volatile("ldmatrix.sync.aligned.m8n8.x2.shared.b16 {%0,%1}, [%2];"
                 : "=r"(b0), "=r"(b1) : "r"(addr));
}
__device__ __forceinline__ void mma_bf16(float* d, const uint32_t* a,
                                         uint32_t b0, uint32_t b1) {
    asm volatile("mma.sync.aligned.m16n8k16.row.col.f32.bf16.bf16.f32 "
                 "{%0,%1,%2,%3}, {%4,%5,%6,%7}, {%8,%9}, {%0,%1,%2,%3};"
                 : "+f"(d[0]), "+f"(d[1]), "+f"(d[2]), "+f"(d[3])
                 : "r"(a[0]), "r"(a[1]), "r"(a[2]), "r"(a[3]), "r"(b0), "r"(b1));
}
// swizzled byte offset inside a 128x128 bf16 tile (row stride 256B,
// 16B chunks XOR-permuted by row&7 -> conflict-free ldmatrix)
__device__ __forceinline__ uint32_t sw(int row, int chunk16) {
    return (uint32_t)(row * 256 + ((chunk16 ^ (row & 7)) << 4));
}
__device__ __forceinline__ uint32_t pack_bf16(__nv_bfloat16 lo, __nv_bfloat16 hi) {
    return ((uint32_t)__bfloat16_as_ushort(hi) << 16) | __bfloat16_as_ushort(lo);
}
// convert 4 floats -> hi/lo bf16x2 pairs, write to swizzled smem images
__device__ __forceinline__ void cvt_store4(char* hiBase, char* loBase,
                                           int r, int c4, float4 v) {
    __nv_bfloat16 h0 = __float2bfloat16_rn(v.x);
    __nv_bfloat16 h1 = __float2bfloat16_rn(v.y);
    __nv_bfloat16 h2 = __float2bfloat16_rn(v.z);
    __nv_bfloat16 h3 = __float2bfloat16_rn(v.w);
    __nv_bfloat16 l0 = __float2bfloat16_rn(v.x - __bfloat162float(h0));
    __nv_bfloat16 l1 = __float2bfloat16_rn(v.y - __bfloat162float(h1));
    __nv_bfloat16 l2 = __float2bfloat16_rn(v.z - __bfloat162float(h2));
    __nv_bfloat16 l3 = __float2bfloat16_rn(v.w - __bfloat162float(h3));
    uint32_t off = sw(r, c4 >> 1) + (c4 & 1) * 8;
    *(uint2*)(hiBase + off) = make_uint2(pack_bf16(h0, h1), pack_bf16(h2, h3));
    *(uint2*)(loBase + off) = make_uint2(pack_bf16(l0, l1), pack_bf16(l2, l3));
}

// ---------------------------------------------------------------------------
// prep: weight images (W1a^T, W1b^T, W1c^T hi/lo, swizzled) + silu table
// ---------------------------------------------------------------------------
extern "C" __global__ void k_prep(const float* __restrict__ W1)
{
    int idx = blockIdx.x * blockDim.x + threadIdx.x;
    if (idx < 24576) {
        int p   = idx >> 13;
        int rem = idx & 8191;
        int f   = rem >> 6;
        int k0  = (rem & 63) * 2;
        float v0 = W1[(p * 128 + k0) * FDIM + f];
        float v1 = W1[(p * 128 + k0 + 1) * FDIM + f];
        __nv_bfloat16 h0 = __float2bfloat16_rn(v0);
        __nv_bfloat16 h1 = __float2bfloat16_rn(v1);
        __nv_bfloat16 l0 = __float2bfloat16_rn(v0 - __bfloat162float(h0));
        __nv_bfloat16 l1 = __float2bfloat16_rn(v1 - __bfloat162float(h1));
        uint32_t off = sw(f, k0 >> 3) + (k0 & 7) * 2;
        *(uint32_t*)((char*)g_img[p][0] + off) = pack_bf16(h0, h1);
        *(uint32_t*)((char*)g_img[p][1] + off) = pack_bf16(l0, l1);
    } else if (idx < 24832) {
        int b = idx - 24576;
        float xc  = -8.0f + ((float)b + 0.5f) * 0.0625f;
        float s   = 1.0f / (1.0f + expf(-xc));
        float sp  = s * (1.0f - s);
        float spp = sp * (1.0f - 2.0f * s);
        float c0  = xc * s;
        float c1  = s + xc * sp;
        float c2  = 0.5f * (2.0f * sp + xc * spp);
        g_tab[b] = make_float4(c0, c1, c2, 0.0f);
    }
}

// ---------------------------------------------------------------------------
// precompute: g_A = x@W1a, g_B = x@W1b  (split-bf16 3-pass mma.sync)
// smem: XHI 0, XLO 32768, BAHI 65536, BALO 98304, BBHI 131072, BBLO 163840
// ---------------------------------------------------------------------------
#define PC_SMEM 196608

extern "C" __global__ void __launch_bounds__(256, 1)
k_precompute_tc(const float* __restrict__ x, int n_nodes)
{
    extern __shared__ char smem[];
    const uint32_t sb = smem_u32(smem);
    const int tid  = threadIdx.x;
    const int wid  = tid >> 5;
    const int lane = tid & 31;
    const int row0 = wid * 16;
    const int grow0 = blockIdx.x * 128;

    // copy 4 weight images (128KB)
    {
        uint4* d0 = (uint4*)(smem + 65536);
        const uint4* s0 = (const uint4*)g_img[0][0];   // contiguous [0][0..1],[1][0..1]
        #pragma unroll
        for (int t = 0; t < 32; ++t) d0[t * 256 + tid] = s0[t * 256 + tid];
    }
    // convert x tile -> XHI/XLO
    #pragma unroll
    for (int it = 0; it < 16; ++it) {
        int idx = it * 256 + tid;
        int r = idx >> 5, c4 = idx & 31;
        int g = grow0 + r;
        float4 v = make_float4(0.f, 0.f, 0.f, 0.f);
        if (g < n_nodes) v = reinterpret_cast<const float4*>(x)[g * 32 + c4];
        cvt_store4(smem, smem + 32768, r, c4, v);
    }
    __syncthreads();

    const uint32_t xr   = lane & 7;
    const uint32_t aoff = sb + ((uint32_t)(row0 + (lane & 15)) << 8);
    const uint32_t acb  = lane >> 4;
    const uint32_t bcb  = (lane >> 3) & 1;
    const uint32_t brow = (uint32_t)(lane & 7) << 8;
    const int q  = lane >> 2;
    const int cL = (lane & 3) * 2;

    for (int part = 0; part < 2; ++part) {
        const uint32_t bhiB = sb + 65536 + part * 65536;
        const uint32_t bloB = bhiB + 32768;
        float acc[16][4];
        #pragma unroll
        for (int n = 0; n < 16; ++n)
            #pragma unroll
            for (int u = 0; u < 4; ++u) acc[n][u] = 0.f;

        for (int k = 0; k < 8; ++k) {
            uint32_t ah[4], al[4];
            uint32_t ca = 2 * k + acb;
            uint32_t ao = ((ca ^ xr) << 4);
            ldsm_x4(ah[0], ah[1], ah[2], ah[3], aoff + ao);
            ldsm_x4(al[0], al[1], al[2], al[3], aoff + 32768 + ao);
            uint32_t cb = 2 * k + bcb;
            uint32_t bo = brow + ((cb ^ xr) << 4);
            #pragma unroll
            for (int nt = 0; nt < 16; ++nt) {
                uint32_t bh0, bh1, bl0, bl1;
                uint32_t nb = bo + (uint32_t)(nt * 8) * 256;
                ldsm_x2(bh0, bh1, bhiB + nb);
                ldsm_x2(bl0, bl1, bloB + nb);
                mma_bf16(acc[nt], ah, bh0, bh1);
                mma_bf16(acc[nt], al, bh0, bh1);
                mma_bf16(acc[nt], ah, bl0, bl1);
            }
        }

        float* dst = part == 0 ? g_A : g_B;
        int g1 = grow0 + row0 + q;
        int g2 = g1 + 8;
        #pragma unroll
        for (int nt = 0; nt < 16; ++nt) {
            int c = nt * 8 + cL;
            if (g1 < n_nodes) *(float2*)(dst + g1 * FDIM + c) = make_float2(acc[nt][0], acc[nt][1]);
            if (g2 < n_nodes) *(float2*)(dst + g2 * FDIM + c) = make_float2(acc[nt][2], acc[nt][3]);
        }
    }
}

// ---------------------------------------------------------------------------
// pair kernel (persistent): per 128-pair tile
//   pre = w_tile @ W1c (3-pass bf16 mma) ; out = silu_tab(pre + gA + gB + b1).W2 + b2
// smem: AHI 0, ALO 32768, BHI 65536, BLO 98304,
//       ADD 131072 (128 x 132 f32), TAB 198656 (4KB), W2 202752 (512B)
// ---------------------------------------------------------------------------
#define KP_SMEM 203264
#define ADD_STRIDE 132

extern "C" __global__ void __launch_bounds__(256, 1)
k_pairs_tc(const float* __restrict__ w_ij,
           const float* __restrict__ b1,
           const float* __restrict__ W2,
           const float* __restrict__ b2,
           const int* __restrict__ idx_i,
           const int* __restrict__ idx_j,
           float* __restrict__ out,
           int n_pairs, int ntiles)
{
    extern __shared__ char smem[];
    const uint32_t sb = smem_u32(smem);
    const int tid  = threadIdx.x;
    const int wid  = tid >> 5;
    const int lane = tid & 31;
    const int row0 = wid * 16;

    float*  sAdd = (float*)(smem + 131072);
    float4* sTab = (float4*)(smem + 198656);
    float*  sW2  = (float*)(smem + 202752);

    // one-time: W1c images, table, W2
    {
        uint4* d0 = (uint4*)(smem + 65536);
        const uint4* s0 = (const uint4*)g_img[2][0];   // hi+lo contiguous 64KB
        #pragma unroll
        for (int t = 0; t < 16; ++t) d0[t * 256 + tid] = s0[t * 256 + tid];
        ((uint4*)sTab)[tid] = ((const uint4*)g_tab)[tid];
        if (tid < 32) ((float4*)sW2)[tid] = ((const float4*)W2)[tid];
    }
    const float b2v = b2[0];

    const uint32_t xr   = lane & 7;
    const uint32_t aoff = sb + ((uint32_t)(row0 + (lane & 15)) << 8);
    const uint32_t acb  = lane >> 4;
    const uint32_t bcb  = (lane >> 3) & 1;
    const uint32_t brow = (uint32_t)(lane & 7) << 8;
    const int q  = lane >> 2;
    const int cL = (lane & 3) * 2;

    for (int tile = blockIdx.x; tile < ntiles; tile += gridDim.x) {
        const int p0 = tile * 128;

        // phase 1: convert w_ij tile + build addend tile (gA+gB+b1)
        #pragma unroll
        for (int it = 0; it < 16; ++it) {
            int idx = it * 256 + tid;
            int r = idx >> 5, c4 = idx & 31;
            int gp = p0 + r;
            float4 v = make_float4(0.f, 0.f, 0.f, 0.f);
            if (gp < n_pairs) v = reinterpret_cast<const float4*>(w_ij)[gp * 32 + c4];
            cvt_store4(smem, smem + 32768, r, c4, v);

            int gpc = gp < n_pairs ? gp : 0;
            int ri = __ldg(idx_i + gpc);
            int rj = __ldg(idx_j + gpc);
            float4 va = reinterpret_cast<const float4*>(g_A)[ri * 32 + c4];
            float4 vb = reinterpret_cast<const float4*>(g_B)[rj * 32 + c4];
            float4 v1 = reinterpret_cast<const float4*>(b1)[c4];
            *(float4*)(sAdd + r * ADD_STRIDE + c4 * 4) =
                make_float4(va.x + vb.x + v1.x, va.y + vb.y + v1.y,
                            va.z + vb.z + v1.z, va.w + vb.w + v1.w);
        }
        __syncthreads();

        // phase 2: MMA (3-pass split bf16)
        float acc[16][4];
        #pragma unroll
        for (int n = 0; n < 16; ++n)
            #pragma unroll
            for (int u = 0; u < 4; ++u) acc[n][u] = 0.f;

        for (int k = 0; k < 8; ++k) {
            uint32_t ah[4], al[4];
            uint32_t ca = 2 * k + acb;
            uint32_t ao = ((ca ^ xr) << 4);
            ldsm_x4(ah[0], ah[1], ah[2], ah[3], aoff + ao);
            ldsm_x4(al[0], al[1], al[2], al[3], aoff + 32768 + ao);
            uint32_t cb = 2 * k + bcb;
            uint32_t bo = brow + ((cb ^ xr) << 4);
            #pragma unroll
            for (int nt = 0; nt < 16; ++nt) {
                uint32_t bh0, bh1, bl0, bl1;
                uint32_t nb = bo + (uint32_t)(nt * 8) * 256;
                ldsm_x2(bh0, bh1, sb + 65536 + nb);
                ldsm_x2(bl0, bl1, sb + 98304 + nb);
                mma_bf16(acc[nt], ah, bh0, bh1);
                mma_bf16(acc[nt], al, bh0, bh1);
                mma_bf16(acc[nt], ah, bl0, bl1);
            }
        }

        // phase 3: fused epilogue (table silu + W2 dot), per-warp rows
        const int r1 = row0 + q;
        const int r2 = r1 + 8;
        float sum1 = 0.f, sum2 = 0.f;
        #pragma unroll
        for (int nt = 0; nt < 16; ++nt) {
            int c = nt * 8 + cL;
            float2 w2 = *(float2*)(sW2 + c);
            float2 a1 = *(float2*)(sAdd + r1 * ADD_STRIDE + c);
            float2 a2 = *(float2*)(sAdd + r2 * ADD_STRIDE + c);
            float vv[4] = { acc[nt][0] + a1.x, acc[nt][1] + a1.y,
                            acc[nt][2] + a2.x, acc[nt][3] + a2.y };
            float ss[4];
            #pragma unroll
            for (int u = 0; u < 4; ++u) {
                float t  = fminf(fmaxf(vv[u], -7.999f), 7.999f);
                int   ib = (int)((t + 8.0f) * 16.0f);
                float xc = fmaf((float)ib, 0.0625f, -7.96875f);
                float dv = t - xc;
                float4 cc = sTab[ib];
                ss[u] = fmaf(fmaf(cc.z, dv, cc.y), dv, cc.x);
            }
            sum1 = fmaf(ss[0], w2.x, fmaf(ss[1], w2.y, sum1));
            sum2 = fmaf(ss[2], w2.x, fmaf(ss[3], w2.y, sum2));
        }
        sum1 += __shfl_xor_sync(0xffffffff, sum1, 1);
        sum1 += __shfl_xor_sync(0xffffffff, sum1, 2);
        sum2 += __shfl_xor_sync(0xffffffff, sum2, 1);
        sum2 += __shfl_xor_sync(0xffffffff, sum2, 2);
        if ((lane & 3) == 0) {
            int g1 = p0 + r1, g2 = p0 + r2;
            if (g1 < n_pairs) out[g1] = sum1 + b2v;
            if (g2 < n_pairs) out[g2] = sum2 + b2v;
        }
        __syncthreads();   // protect smem before next tile overwrites
    }
}

// ---------------------------------------------------------------------------
extern "C" void kernel_launch(void* const* d_in, const int* in_sizes, int n_in,
                              void* d_out, int out_size)
{
    const float* x     = (const float*)d_in[0];
    const float* w_ij  = (const float*)d_in[1];
    const float* W1    = (const float*)d_in[2];
    const float* b1    = (const float*)d_in[3];
    const float* W2    = (const float*)d_in[4];
    const float* b2    = (const float*)d_in[5];
    const int*   idx_i = (const int*)d_in[6];
    const int*   idx_j = (const int*)d_in[7];
    float* out = (float*)d_out;

    const int n_nodes = in_sizes[0] / FDIM;
    const int n_pairs = out_size;
    const int ntiles  = (n_pairs + 127) / 128;

    cudaFuncSetAttribute(k_precompute_tc, cudaFuncAttributeMaxDynamicSharedMemorySize, PC_SMEM);
    cudaFuncSetAttribute(k_pairs_tc,      cudaFuncAttributeMaxDynamicSharedMemorySize, KP_SMEM);

    int nsm = 148;
    cudaDeviceGetAttribute(&nsm, cudaDevAttrMultiProcessorCount, 0);
    if (nsm <= 0) nsm = 148;
    int grid2 = nsm < ntiles ? nsm : ntiles;

    k_prep<<<97, 256>>>(W1);
    k_precompute_tc<<<(n_nodes + 127) / 128, 256, PC_SMEM>>>(x, n_nodes);
    k_pairs_tc<<<grid2, 256, KP_SMEM>>>(w_ij, b1, W2, b2, idx_i, idx_j,
                                        out, n_pairs, ntiles);
}